// round 1
// baseline (speedup 1.0000x reference)
#include <cuda_runtime.h>
#include <math.h>
#include <stdint.h>

// ---------------- problem constants ----------------
#define T_TOK     8192
#define DMODEL    1024
#define DFF       4096
#define E_ROUTED  7
#define TOPK      2
#define CAPACITY  2926
#define SHARED_SCALE 1.0f

// ---------------- scratch (device globals; no allocation allowed) ----------
__device__ float g_h[T_TOK * DMODEL];                      // 32 MB  LN output
__device__ int   g_topidx[T_TOK * TOPK];
__device__ float g_gate[T_TOK * TOPK];
__device__ int   g_pos[TOPK * T_TOK];                      // slot or -1
__device__ int   g_slot_token[E_ROUTED * CAPACITY];        // gather list
__device__ int   g_count[E_ROUTED];
__device__ float g_ub[E_ROUTED * CAPACITY * DFF];          // 336 MB  b then u (in-place)
__device__ float g_ubs[T_TOK * DFF];                       // 128 MB  shared b/u
__device__ float g_ye[E_ROUTED * CAPACITY * DMODEL];       // 84 MB
__device__ float g_ys[T_TOK * DMODEL];                     // 32 MB

// ---------------- helpers ----------------
__device__ __forceinline__ float silu_f(float v) {
    return v / (1.0f + __expf(-v));
}

__device__ __forceinline__ float blockReduceSum256(float v, float* sh8) {
    int lane = threadIdx.x & 31, wid = threadIdx.x >> 5;
    #pragma unroll
    for (int o = 16; o; o >>= 1) v += __shfl_down_sync(0xffffffffu, v, o);
    if (lane == 0) sh8[wid] = v;
    __syncthreads();
    float r = (threadIdx.x < 8) ? sh8[threadIdx.x] : 0.0f;
    if (wid == 0) {
        #pragma unroll
        for (int o = 4; o; o >>= 1) r += __shfl_down_sync(0xffffffffu, r, o);
        if (lane == 0) sh8[0] = r;
    }
    __syncthreads();
    float res = sh8[0];
    __syncthreads();
    return res;
}

// ---------------- 1) LayerNorm: x -> g_h ----------------
__global__ void ln_kernel(const float* __restrict__ x,
                          const float* __restrict__ gamma,
                          const float* __restrict__ beta) {
    __shared__ float sh[8];
    int t = blockIdx.x;
    int d4 = threadIdx.x;                 // 256 threads * float4 = 1024
    float4 v = reinterpret_cast<const float4*>(x + (size_t)t * DMODEL)[d4];
    float s = v.x + v.y + v.z + v.w;
    float mu = blockReduceSum256(s, sh) * (1.0f / DMODEL);
    float dx = v.x - mu, dy = v.y - mu, dz = v.z - mu, dw = v.w - mu;
    float sq = dx * dx + dy * dy + dz * dz + dw * dw;
    float var = blockReduceSum256(sq, sh) * (1.0f / DMODEL);
    float inv = rsqrtf(var + 1e-5f);
    float4 gg = reinterpret_cast<const float4*>(gamma)[d4];
    float4 bb = reinterpret_cast<const float4*>(beta)[d4];
    float4 o;
    o.x = dx * inv * gg.x + bb.x;
    o.y = dy * inv * gg.y + bb.y;
    o.z = dz * inv * gg.z + bb.z;
    o.w = dw * inv * gg.w + bb.w;
    reinterpret_cast<float4*>(g_h + (size_t)t * DMODEL)[d4] = o;
}

// ---------------- 2) Router: logits = h @ Wr, top-2 + softmax ------------
__global__ void router_kernel(const float* __restrict__ Wr) {
    int gw = (blockIdx.x * blockDim.x + threadIdx.x) >> 5;   // token id
    int lane = threadIdx.x & 31;
    if (gw >= T_TOK) return;
    const float* hrow = g_h + (size_t)gw * DMODEL;
    double acc[E_ROUTED];
    #pragma unroll
    for (int e = 0; e < E_ROUTED; e++) acc[e] = 0.0;
    for (int d = lane; d < DMODEL; d += 32) {
        float hv = hrow[d];
        const float* wrow = Wr + (size_t)d * E_ROUTED;
        #pragma unroll
        for (int e = 0; e < E_ROUTED; e++)
            acc[e] += (double)hv * (double)wrow[e];
    }
    #pragma unroll
    for (int e = 0; e < E_ROUTED; e++) {
        #pragma unroll
        for (int o = 16; o; o >>= 1)
            acc[e] += __shfl_down_sync(0xffffffffu, acc[e], o);
    }
    if (lane == 0) {
        float v[E_ROUTED];
        #pragma unroll
        for (int e = 0; e < E_ROUTED; e++) v[e] = (float)acc[e];
        int i1 = 0;
        #pragma unroll
        for (int e = 1; e < E_ROUTED; e++) if (v[e] > v[i1]) i1 = e;
        int i2 = -1;
        #pragma unroll
        for (int e = 0; e < E_ROUTED; e++) {
            if (e == i1) continue;
            if (i2 < 0 || v[e] > v[i2]) i2 = e;
        }
        float m = v[i1];
        float e1 = expf(v[i1] - m);
        float e2 = expf(v[i2] - m);
        float inv = 1.0f / (e1 + e2);
        g_topidx[gw * 2 + 0] = i1;
        g_topidx[gw * 2 + 1] = i2;
        g_gate[gw * 2 + 0] = e1 * inv;
        g_gate[gw * 2 + 1] = e2 * inv;
    }
}

// ---------------- 3) Dispatch positions (k-major cumulative, capacity) ----
__global__ void pos_kernel() {
    int e = blockIdx.x;                 // one block per expert
    __shared__ int warpTot[8];
    int lane = threadIdx.x & 31, wid = threadIdx.x >> 5;
    int running = 0;
    for (int k = 0; k < TOPK; k++) {
        for (int base = 0; base < T_TOK; base += 256) {
            int t = base + threadIdx.x;
            int match = (g_topidx[t * 2 + k] == e) ? 1 : 0;
            unsigned bal = __ballot_sync(0xffffffffu, match);
            int wpre = __popc(bal & ((1u << lane) - 1u));
            if (lane == 31) warpTot[wid] = wpre + match;
            __syncthreads();
            int wbase = 0;
            #pragma unroll
            for (int w = 0; w < 8; w++) if (w < wid) wbase += warpTot[w];
            if (match) {
                int p = running + wbase + wpre;
                if (p < CAPACITY) {
                    g_pos[k * T_TOK + t] = p;
                    g_slot_token[e * CAPACITY + p] = t;
                } else {
                    g_pos[k * T_TOK + t] = -1;
                }
            }
            int tot = 0;
            #pragma unroll
            for (int w = 0; w < 8; w++) tot += warpTot[w];
            running += tot;
            __syncthreads();
        }
    }
    if (threadIdx.x == 0) g_count[e] = (running < CAPACITY) ? running : CAPACITY;
}

// ---------------- SGEMM tile body: 128x128x16, 256 thr, 8x8 micro --------
#define BM 128
#define BN 128
#define BK 16

__device__ __forceinline__ void sgemm_tile(
    const float* __restrict__ A, int lda,
    const int* __restrict__ gather,
    const float* __restrict__ B, int N, int K,
    float* __restrict__ C,
    int Mlimit, int Mstore, int m0, int n0, int fuse)
{
    __shared__ float As[BK][BM];
    __shared__ float Bs[BK][BN];

    const int tid = threadIdx.x;
    const int tx = tid & 15;
    const int ty = tid >> 4;

    // A-tile load mapping: thread loads 8 contiguous K-floats of one M-row
    const int mload = tid >> 1;             // 0..127
    const int kbase = (tid & 1) * 8;        // 0 or 8
    int mg = m0 + mload;
    int arow = 0;
    if (mg < Mlimit) arow = gather ? gather[mg] : mg;
    const float* Aptr = A + (size_t)arow * lda + kbase;

    // B-tile load mapping: thread loads 8 contiguous N-floats of one K-row
    const float* Bbase = B + (size_t)ty * N + n0 + tx * 8;

    float acc[8][8];
    #pragma unroll
    for (int i = 0; i < 8; i++)
        #pragma unroll
        for (int j = 0; j < 8; j++) acc[i][j] = 0.0f;

    for (int k0 = 0; k0 < K; k0 += BK) {
        float4 va0 = *(const float4*)(Aptr + k0);
        float4 va1 = *(const float4*)(Aptr + k0 + 4);
        const float* bp = Bbase + (size_t)k0 * N;
        float4 vb0 = *(const float4*)(bp);
        float4 vb1 = *(const float4*)(bp + 4);

        __syncthreads();
        As[kbase + 0][mload] = va0.x;
        As[kbase + 1][mload] = va0.y;
        As[kbase + 2][mload] = va0.z;
        As[kbase + 3][mload] = va0.w;
        As[kbase + 4][mload] = va1.x;
        As[kbase + 5][mload] = va1.y;
        As[kbase + 6][mload] = va1.z;
        As[kbase + 7][mload] = va1.w;
        *(float4*)&Bs[ty][tx * 8]     = vb0;
        *(float4*)&Bs[ty][tx * 8 + 4] = vb1;
        __syncthreads();

        #pragma unroll
        for (int kk = 0; kk < BK; kk++) {
            float a[8], b[8];
            *(float4*)&a[0] = *(const float4*)&As[kk][ty * 8];
            *(float4*)&a[4] = *(const float4*)&As[kk][ty * 8 + 4];
            *(float4*)&b[0] = *(const float4*)&Bs[kk][tx * 8];
            *(float4*)&b[4] = *(const float4*)&Bs[kk][tx * 8 + 4];
            #pragma unroll
            for (int i = 0; i < 8; i++)
                #pragma unroll
                for (int j = 0; j < 8; j++)
                    acc[i][j] = fmaf(a[i], b[j], acc[i][j]);
        }
    }

    #pragma unroll
    for (int i = 0; i < 8; i++) {
        int mgs = m0 + ty * 8 + i;
        if (mgs >= Mstore) continue;
        float* crow = C + (size_t)mgs * N + n0 + tx * 8;
        if (fuse) {
            float4 p0 = *(const float4*)(crow);
            float4 p1 = *(const float4*)(crow + 4);
            float4 o0, o1;
            o0.x = silu_f(acc[i][0]) * p0.x;
            o0.y = silu_f(acc[i][1]) * p0.y;
            o0.z = silu_f(acc[i][2]) * p0.z;
            o0.w = silu_f(acc[i][3]) * p0.w;
            o1.x = silu_f(acc[i][4]) * p1.x;
            o1.y = silu_f(acc[i][5]) * p1.y;
            o1.z = silu_f(acc[i][6]) * p1.z;
            o1.w = silu_f(acc[i][7]) * p1.w;
            *(float4*)(crow)     = o0;
            *(float4*)(crow + 4) = o1;
        } else {
            float4 o0, o1;
            o0.x = acc[i][0]; o0.y = acc[i][1]; o0.z = acc[i][2]; o0.w = acc[i][3];
            o1.x = acc[i][4]; o1.y = acc[i][5]; o1.z = acc[i][6]; o1.w = acc[i][7];
            *(float4*)(crow)     = o0;
            *(float4*)(crow + 4) = o1;
        }
    }
}

// ---------------- 4) W3/W1 grouped GEMM (z = expert, z==7 -> shared) -----
__global__ __launch_bounds__(256, 2) void gemm13_kernel(
    const float* __restrict__ Wrouted,   // [7, D, F]
    const float* __restrict__ Wshared,   // [D, F]
    int fuse)                            // 0: store b; 1: u = silu(a)*b in-place
{
    int e = blockIdx.z;
    int m0 = blockIdx.y * BM;
    int n0 = blockIdx.x * BN;
    if (e < E_ROUTED) {
        int cnt = g_count[e];
        if (m0 >= cnt) return;
        sgemm_tile(g_h, DMODEL, g_slot_token + e * CAPACITY,
                   Wrouted + (size_t)e * DMODEL * DFF, DFF, DMODEL,
                   g_ub + (size_t)e * CAPACITY * DFF,
                   cnt, CAPACITY, m0, n0, fuse);
    } else {
        sgemm_tile(g_h, DMODEL, nullptr, Wshared, DFF, DMODEL,
                   g_ubs, T_TOK, T_TOK, m0, n0, fuse);
    }
}

// ---------------- 5) W2 grouped GEMM --------------------------------------
__global__ __launch_bounds__(256, 2) void gemm2_kernel(
    const float* __restrict__ W2,        // [7, F, D]
    const float* __restrict__ W2s)       // [F, D]
{
    int e = blockIdx.z;
    int m0 = blockIdx.y * BM;
    int n0 = blockIdx.x * BN;
    if (e < E_ROUTED) {
        int cnt = g_count[e];
        if (m0 >= cnt) return;
        sgemm_tile(g_ub + (size_t)e * CAPACITY * DFF, DFF, nullptr,
                   W2 + (size_t)e * DFF * DMODEL, DMODEL, DFF,
                   g_ye + (size_t)e * CAPACITY * DMODEL,
                   cnt, CAPACITY, m0, n0, 0);
    } else {
        sgemm_tile(g_ubs, DFF, nullptr, W2s, DMODEL, DFF,
                   g_ys, T_TOK, T_TOK, m0, n0, 0);
    }
}

// ---------------- 6) Combine: out = shared + sum_k gate*ye ---------------
__global__ void combine_kernel(float* __restrict__ out) {
    int t = blockIdx.x;
    int d4 = threadIdx.x;   // 256 * float4 = 1024
    float4 o = reinterpret_cast<const float4*>(g_ys + (size_t)t * DMODEL)[d4];
    o.x *= SHARED_SCALE; o.y *= SHARED_SCALE; o.z *= SHARED_SCALE; o.w *= SHARED_SCALE;
    #pragma unroll
    for (int k = 0; k < TOPK; k++) {
        int p = g_pos[k * T_TOK + t];
        if (p >= 0) {
            int e = g_topidx[t * 2 + k];
            float gv = g_gate[t * 2 + k];
            float4 y = reinterpret_cast<const float4*>(
                g_ye + ((size_t)e * CAPACITY + p) * DMODEL)[d4];
            o.x += gv * y.x;
            o.y += gv * y.y;
            o.z += gv * y.z;
            o.w += gv * y.w;
        }
    }
    reinterpret_cast<float4*>(out + (size_t)t * DMODEL)[d4] = o;
}

// ---------------- launch ---------------------------------------------------
extern "C" void kernel_launch(void* const* d_in, const int* in_sizes, int n_in,
                              void* d_out, int out_size) {
    (void)in_sizes; (void)n_in; (void)out_size;
    const float* x    = (const float*)d_in[0];
    const float* ln_g = (const float*)d_in[1];
    const float* ln_b = (const float*)d_in[2];
    const float* Wr   = (const float*)d_in[3];
    const float* W1   = (const float*)d_in[4];
    const float* W3   = (const float*)d_in[5];
    const float* W2   = (const float*)d_in[6];
    const float* W1s  = (const float*)d_in[7];
    const float* W3s  = (const float*)d_in[8];
    const float* W2s  = (const float*)d_in[9];
    float* out = (float*)d_out;

    ln_kernel<<<T_TOK, 256>>>(x, ln_g, ln_b);
    router_kernel<<<T_TOK / 8, 256>>>(Wr);
    pos_kernel<<<E_ROUTED, 256>>>();

    dim3 g13(DFF / BN, T_TOK / BM, E_ROUTED + 1);   // (32, 64, 8)
    gemm13_kernel<<<g13, 256>>>(W3, W3s, 0);        // b = xe @ W3
    gemm13_kernel<<<g13, 256>>>(W1, W1s, 1);        // u = silu(xe @ W1) * b

    dim3 g2(DMODEL / BN, T_TOK / BM, E_ROUTED + 1); // (8, 64, 8)
    gemm2_kernel<<<g2, 256>>>(W2, W2s);             // ye = u @ W2

    combine_kernel<<<T_TOK, 256>>>(out);
}

// round 2
// speedup vs baseline: 1.0001x; 1.0001x over previous
#include <cuda_runtime.h>
#include <math.h>
#include <stdint.h>

// ---------------- problem constants ----------------
#define T_TOK     8192
#define DMODEL    1024
#define DFF       4096
#define E_ROUTED  7
#define TOPK      2
#define CAPACITY  2926
#define SHARED_SCALE 1.0f

// ---------------- scratch (device globals; no allocation allowed) ----------
__device__ float g_h[T_TOK * DMODEL];                      // 32 MB  LN output
__device__ int   g_topidx[T_TOK * TOPK];
__device__ float g_gate[T_TOK * TOPK];
__device__ int   g_pos[TOPK * T_TOK];                      // slot or -1
__device__ int   g_slot_token[E_ROUTED * CAPACITY];        // gather list
__device__ int   g_count[E_ROUTED];
__device__ float g_ub[E_ROUTED * CAPACITY * DFF];          // 336 MB  b then u (in-place)
__device__ float g_ubs[T_TOK * DFF];                       // 128 MB  shared b/u
__device__ float g_ye[E_ROUTED * CAPACITY * DMODEL];       // 84 MB
__device__ float g_ys[T_TOK * DMODEL];                     // 32 MB

// ---------------- helpers ----------------
__device__ __forceinline__ float silu_f(float v) {
    return v / (1.0f + __expf(-v));
}

__device__ __forceinline__ float blockReduceSum256(float v, float* sh8) {
    int lane = threadIdx.x & 31, wid = threadIdx.x >> 5;
    #pragma unroll
    for (int o = 16; o; o >>= 1) v += __shfl_down_sync(0xffffffffu, v, o);
    if (lane == 0) sh8[wid] = v;
    __syncthreads();
    float r = (threadIdx.x < 8) ? sh8[threadIdx.x] : 0.0f;
    if (wid == 0) {
        #pragma unroll
        for (int o = 4; o; o >>= 1) r += __shfl_down_sync(0xffffffffu, r, o);
        if (lane == 0) sh8[0] = r;
    }
    __syncthreads();
    float res = sh8[0];
    __syncthreads();
    return res;
}

// ---------------- 1) LayerNorm: x -> g_h ----------------
__global__ void ln_kernel(const float* __restrict__ x,
                          const float* __restrict__ gamma,
                          const float* __restrict__ beta) {
    __shared__ float sh[8];
    int t = blockIdx.x;
    int d4 = threadIdx.x;                 // 256 threads * float4 = 1024
    float4 v = reinterpret_cast<const float4*>(x + (size_t)t * DMODEL)[d4];
    float s = v.x + v.y + v.z + v.w;
    float mu = blockReduceSum256(s, sh) * (1.0f / DMODEL);
    float dx = v.x - mu, dy = v.y - mu, dz = v.z - mu, dw = v.w - mu;
    float sq = dx * dx + dy * dy + dz * dz + dw * dw;
    float var = blockReduceSum256(sq, sh) * (1.0f / DMODEL);
    float inv = rsqrtf(var + 1e-5f);
    float4 gg = reinterpret_cast<const float4*>(gamma)[d4];
    float4 bb = reinterpret_cast<const float4*>(beta)[d4];
    float4 o;
    o.x = dx * inv * gg.x + bb.x;
    o.y = dy * inv * gg.y + bb.y;
    o.z = dz * inv * gg.z + bb.z;
    o.w = dw * inv * gg.w + bb.w;
    reinterpret_cast<float4*>(g_h + (size_t)t * DMODEL)[d4] = o;
}

// ---------------- 2) Router: logits = h @ Wr, top-2 + softmax ------------
__global__ void router_kernel(const float* __restrict__ Wr) {
    int gw = (blockIdx.x * blockDim.x + threadIdx.x) >> 5;   // token id
    int lane = threadIdx.x & 31;
    if (gw >= T_TOK) return;
    const float* hrow = g_h + (size_t)gw * DMODEL;
    double acc[E_ROUTED];
    #pragma unroll
    for (int e = 0; e < E_ROUTED; e++) acc[e] = 0.0;
    for (int d = lane; d < DMODEL; d += 32) {
        float hv = hrow[d];
        const float* wrow = Wr + (size_t)d * E_ROUTED;
        #pragma unroll
        for (int e = 0; e < E_ROUTED; e++)
            acc[e] += (double)hv * (double)wrow[e];
    }
    #pragma unroll
    for (int e = 0; e < E_ROUTED; e++) {
        #pragma unroll
        for (int o = 16; o; o >>= 1)
            acc[e] += __shfl_down_sync(0xffffffffu, acc[e], o);
    }
    if (lane == 0) {
        float v[E_ROUTED];
        #pragma unroll
        for (int e = 0; e < E_ROUTED; e++) v[e] = (float)acc[e];
        int i1 = 0;
        #pragma unroll
        for (int e = 1; e < E_ROUTED; e++) if (v[e] > v[i1]) i1 = e;
        int i2 = -1;
        #pragma unroll
        for (int e = 0; e < E_ROUTED; e++) {
            if (e == i1) continue;
            if (i2 < 0 || v[e] > v[i2]) i2 = e;
        }
        float m = v[i1];
        float e1 = expf(v[i1] - m);
        float e2 = expf(v[i2] - m);
        float inv = 1.0f / (e1 + e2);
        g_topidx[gw * 2 + 0] = i1;
        g_topidx[gw * 2 + 1] = i2;
        g_gate[gw * 2 + 0] = e1 * inv;
        g_gate[gw * 2 + 1] = e2 * inv;
    }
}

// ---------------- 3) Dispatch positions (k-major cumulative, capacity) ----
__global__ void pos_kernel() {
    int e = blockIdx.x;                 // one block per expert
    __shared__ int warpTot[8];
    int lane = threadIdx.x & 31, wid = threadIdx.x >> 5;
    int running = 0;
    for (int k = 0; k < TOPK; k++) {
        for (int base = 0; base < T_TOK; base += 256) {
            int t = base + threadIdx.x;
            int match = (g_topidx[t * 2 + k] == e) ? 1 : 0;
            unsigned bal = __ballot_sync(0xffffffffu, match);
            int wpre = __popc(bal & ((1u << lane) - 1u));
            if (lane == 31) warpTot[wid] = wpre + match;
            __syncthreads();
            int wbase = 0;
            #pragma unroll
            for (int w = 0; w < 8; w++) if (w < wid) wbase += warpTot[w];
            if (match) {
                int p = running + wbase + wpre;
                if (p < CAPACITY) {
                    g_pos[k * T_TOK + t] = p;
                    g_slot_token[e * CAPACITY + p] = t;
                } else {
                    g_pos[k * T_TOK + t] = -1;
                }
            }
            int tot = 0;
            #pragma unroll
            for (int w = 0; w < 8; w++) tot += warpTot[w];
            running += tot;
            __syncthreads();
        }
    }
    if (threadIdx.x == 0) g_count[e] = (running < CAPACITY) ? running : CAPACITY;
}

// ---------------- SGEMM tile body: 128x128x16, 256 thr, 8x8 micro --------
#define BM 128
#define BN 128
#define BK 16

__device__ __forceinline__ void sgemm_tile(
    const float* __restrict__ A, int lda,
    const int* __restrict__ gather,
    const float* __restrict__ B, int N, int K,
    float* __restrict__ C,
    int Mlimit, int Mstore, int m0, int n0, int fuse)
{
    __shared__ float As[BK][BM];
    __shared__ float Bs[BK][BN];

    const int tid = threadIdx.x;
    const int tx = tid & 15;
    const int ty = tid >> 4;

    // A-tile load mapping: thread loads 8 contiguous K-floats of one M-row
    const int mload = tid >> 1;             // 0..127
    const int kbase = (tid & 1) * 8;        // 0 or 8
    int mg = m0 + mload;
    int arow = 0;
    if (mg < Mlimit) arow = gather ? gather[mg] : mg;
    const float* Aptr = A + (size_t)arow * lda + kbase;

    // B-tile load mapping: thread loads 8 contiguous N-floats of one K-row
    const float* Bbase = B + (size_t)ty * N + n0 + tx * 8;

    float acc[8][8];
    #pragma unroll
    for (int i = 0; i < 8; i++)
        #pragma unroll
        for (int j = 0; j < 8; j++) acc[i][j] = 0.0f;

    for (int k0 = 0; k0 < K; k0 += BK) {
        float4 va0 = *(const float4*)(Aptr + k0);
        float4 va1 = *(const float4*)(Aptr + k0 + 4);
        const float* bp = Bbase + (size_t)k0 * N;
        float4 vb0 = *(const float4*)(bp);
        float4 vb1 = *(const float4*)(bp + 4);

        __syncthreads();
        As[kbase + 0][mload] = va0.x;
        As[kbase + 1][mload] = va0.y;
        As[kbase + 2][mload] = va0.z;
        As[kbase + 3][mload] = va0.w;
        As[kbase + 4][mload] = va1.x;
        As[kbase + 5][mload] = va1.y;
        As[kbase + 6][mload] = va1.z;
        As[kbase + 7][mload] = va1.w;
        *(float4*)&Bs[ty][tx * 8]     = vb0;
        *(float4*)&Bs[ty][tx * 8 + 4] = vb1;
        __syncthreads();

        #pragma unroll
        for (int kk = 0; kk < BK; kk++) {
            float a[8], b[8];
            *(float4*)&a[0] = *(const float4*)&As[kk][ty * 8];
            *(float4*)&a[4] = *(const float4*)&As[kk][ty * 8 + 4];
            *(float4*)&b[0] = *(const float4*)&Bs[kk][tx * 8];
            *(float4*)&b[4] = *(const float4*)&Bs[kk][tx * 8 + 4];
            #pragma unroll
            for (int i = 0; i < 8; i++)
                #pragma unroll
                for (int j = 0; j < 8; j++)
                    acc[i][j] = fmaf(a[i], b[j], acc[i][j]);
        }
    }

    #pragma unroll
    for (int i = 0; i < 8; i++) {
        int mgs = m0 + ty * 8 + i;
        if (mgs >= Mstore) continue;
        float* crow = C + (size_t)mgs * N + n0 + tx * 8;
        if (fuse) {
            float4 p0 = *(const float4*)(crow);
            float4 p1 = *(const float4*)(crow + 4);
            float4 o0, o1;
            o0.x = silu_f(acc[i][0]) * p0.x;
            o0.y = silu_f(acc[i][1]) * p0.y;
            o0.z = silu_f(acc[i][2]) * p0.z;
            o0.w = silu_f(acc[i][3]) * p0.w;
            o1.x = silu_f(acc[i][4]) * p1.x;
            o1.y = silu_f(acc[i][5]) * p1.y;
            o1.z = silu_f(acc[i][6]) * p1.z;
            o1.w = silu_f(acc[i][7]) * p1.w;
            *(float4*)(crow)     = o0;
            *(float4*)(crow + 4) = o1;
        } else {
            float4 o0, o1;
            o0.x = acc[i][0]; o0.y = acc[i][1]; o0.z = acc[i][2]; o0.w = acc[i][3];
            o1.x = acc[i][4]; o1.y = acc[i][5]; o1.z = acc[i][6]; o1.w = acc[i][7];
            *(float4*)(crow)     = o0;
            *(float4*)(crow + 4) = o1;
        }
    }
}

// ---------------- 4) W3/W1 grouped GEMM (z = expert, z==7 -> shared) -----
__global__ __launch_bounds__(256, 2) void gemm13_kernel(
    const float* __restrict__ Wrouted,   // [7, D, F]
    const float* __restrict__ Wshared,   // [D, F]
    int fuse)                            // 0: store b; 1: u = silu(a)*b in-place
{
    int e = blockIdx.z;
    int m0 = blockIdx.y * BM;
    int n0 = blockIdx.x * BN;
    if (e < E_ROUTED) {
        int cnt = g_count[e];
        if (m0 >= cnt) return;
        sgemm_tile(g_h, DMODEL, g_slot_token + e * CAPACITY,
                   Wrouted + (size_t)e * DMODEL * DFF, DFF, DMODEL,
                   g_ub + (size_t)e * CAPACITY * DFF,
                   cnt, CAPACITY, m0, n0, fuse);
    } else {
        sgemm_tile(g_h, DMODEL, nullptr, Wshared, DFF, DMODEL,
                   g_ubs, T_TOK, T_TOK, m0, n0, fuse);
    }
}

// ---------------- 5) W2 grouped GEMM --------------------------------------
__global__ __launch_bounds__(256, 2) void gemm2_kernel(
    const float* __restrict__ W2,        // [7, F, D]
    const float* __restrict__ W2s)       // [F, D]
{
    int e = blockIdx.z;
    int m0 = blockIdx.y * BM;
    int n0 = blockIdx.x * BN;
    if (e < E_ROUTED) {
        int cnt = g_count[e];
        if (m0 >= cnt) return;
        sgemm_tile(g_ub + (size_t)e * CAPACITY * DFF, DFF, nullptr,
                   W2 + (size_t)e * DFF * DMODEL, DMODEL, DFF,
                   g_ye + (size_t)e * CAPACITY * DMODEL,
                   cnt, CAPACITY, m0, n0, 0);
    } else {
        sgemm_tile(g_ubs, DFF, nullptr, W2s, DMODEL, DFF,
                   g_ys, T_TOK, T_TOK, m0, n0, 0);
    }
}

// ---------------- 6) Combine: out = shared + sum_k gate*ye ---------------
__global__ void combine_kernel(float* __restrict__ out) {
    int t = blockIdx.x;
    int d4 = threadIdx.x;   // 256 * float4 = 1024
    float4 o = reinterpret_cast<const float4*>(g_ys + (size_t)t * DMODEL)[d4];
    o.x *= SHARED_SCALE; o.y *= SHARED_SCALE; o.z *= SHARED_SCALE; o.w *= SHARED_SCALE;
    #pragma unroll
    for (int k = 0; k < TOPK; k++) {
        int p = g_pos[k * T_TOK + t];
        if (p >= 0) {
            int e = g_topidx[t * 2 + k];
            float gv = g_gate[t * 2 + k];
            float4 y = reinterpret_cast<const float4*>(
                g_ye + ((size_t)e * CAPACITY + p) * DMODEL)[d4];
            o.x += gv * y.x;
            o.y += gv * y.y;
            o.z += gv * y.z;
            o.w += gv * y.w;
        }
    }
    reinterpret_cast<float4*>(out + (size_t)t * DMODEL)[d4] = o;
}

// ---------------- launch ---------------------------------------------------
extern "C" void kernel_launch(void* const* d_in, const int* in_sizes, int n_in,
                              void* d_out, int out_size) {
    (void)in_sizes; (void)n_in; (void)out_size;
    const float* x    = (const float*)d_in[0];
    const float* ln_g = (const float*)d_in[1];
    const float* ln_b = (const float*)d_in[2];
    const float* Wr   = (const float*)d_in[3];
    const float* W1   = (const float*)d_in[4];
    const float* W3   = (const float*)d_in[5];
    const float* W2   = (const float*)d_in[6];
    const float* W1s  = (const float*)d_in[7];
    const float* W3s  = (const float*)d_in[8];
    const float* W2s  = (const float*)d_in[9];
    float* out = (float*)d_out;

    ln_kernel<<<T_TOK, 256>>>(x, ln_g, ln_b);
    router_kernel<<<T_TOK / 8, 256>>>(Wr);
    pos_kernel<<<E_ROUTED, 256>>>();

    dim3 g13(DFF / BN, T_TOK / BM, E_ROUTED + 1);   // (32, 64, 8)
    gemm13_kernel<<<g13, 256>>>(W3, W3s, 0);        // b = xe @ W3
    gemm13_kernel<<<g13, 256>>>(W1, W1s, 1);        // u = silu(xe @ W1) * b

    dim3 g2(DMODEL / BN, T_TOK / BM, E_ROUTED + 1); // (8, 64, 8)
    gemm2_kernel<<<g2, 256>>>(W2, W2s);             // ye = u @ W2

    combine_kernel<<<T_TOK, 256>>>(out);
}

// round 4
// speedup vs baseline: 2.8122x; 2.8118x over previous
#include <cuda_runtime.h>
#include <math.h>
#include <stdint.h>

#define T_TOK     8192
#define DMODEL    1024
#define DFF       4096
#define E_ROUTED  7
#define TOPK      2
#define CAPACITY  2926

// ---------------- scratch ----------------
__device__ float g_h [(size_t)T_TOK * DMODEL];   // exact LN output (router)
__device__ float g_ht[(size_t)T_TOK * DMODEL];   // tf32-rounded LN output (GEMM A)
__device__ int   g_topidx[T_TOK * TOPK];
__device__ float g_gate[T_TOK * TOPK];
__device__ int   g_pos[TOPK * T_TOK];
__device__ int   g_slot_token[E_ROUTED * CAPACITY];
__device__ int   g_count[E_ROUTED];
__device__ float g_W1t[(size_t)8 * DFF * DMODEL];   // [e][F][D] K-major, tf32-rounded
__device__ float g_W3t[(size_t)8 * DFF * DMODEL];
__device__ float g_W2t[(size_t)8 * DMODEL * DFF];   // [e][D][F] K-major, tf32-rounded
__device__ float g_ub [(size_t)E_ROUTED * CAPACITY * DFF];  // u = silu(a)*b (tf32-rounded)
__device__ float g_ubs[(size_t)T_TOK * DFF];
__device__ float g_ye [(size_t)E_ROUTED * CAPACITY * DMODEL];
__device__ float g_ys [(size_t)T_TOK * DMODEL];

// ---------------- helpers ----------------
__device__ __forceinline__ uint32_t smem_u32(const void* p) {
    return (uint32_t)__cvta_generic_to_shared(p);
}
__device__ __forceinline__ float tf32r(float x) {
    uint32_t u;
    asm("cvt.rna.tf32.f32 %0, %1;" : "=r"(u) : "f"(x));
    return __uint_as_float(u);
}
__device__ __forceinline__ void cp16(uint32_t d, const float* s) {
    asm volatile("cp.async.cg.shared.global [%0], [%1], 16;" :: "r"(d), "l"(s) : "memory");
}
__device__ __forceinline__ void cp_commit() {
    asm volatile("cp.async.commit_group;" ::: "memory");
}
template <int N>
__device__ __forceinline__ void cp_wait() {
    asm volatile("cp.async.wait_group %0;" :: "n"(N) : "memory");
}
__device__ __forceinline__ void mma_tf32(float c[4], uint32_t a0, uint32_t a1,
                                         uint32_t a2, uint32_t a3,
                                         uint32_t b0, uint32_t b1) {
    asm volatile(
        "mma.sync.aligned.m16n8k8.row.col.f32.tf32.tf32.f32 "
        "{%0,%1,%2,%3},{%4,%5,%6,%7},{%8,%9},{%0,%1,%2,%3};"
        : "+f"(c[0]), "+f"(c[1]), "+f"(c[2]), "+f"(c[3])
        : "r"(a0), "r"(a1), "r"(a2), "r"(a3), "r"(b0), "r"(b1));
}
__device__ __forceinline__ float silu_f(float v) { return v / (1.0f + __expf(-v)); }

// ---------------- LayerNorm ----------------
__device__ __forceinline__ float blockReduceSum256(float v, float* sh8) {
    int lane = threadIdx.x & 31, wid = threadIdx.x >> 5;
    #pragma unroll
    for (int o = 16; o; o >>= 1) v += __shfl_down_sync(0xffffffffu, v, o);
    if (lane == 0) sh8[wid] = v;
    __syncthreads();
    float r = (threadIdx.x < 8) ? sh8[threadIdx.x] : 0.0f;
    if (wid == 0) {
        #pragma unroll
        for (int o = 4; o; o >>= 1) r += __shfl_down_sync(0xffffffffu, r, o);
        if (lane == 0) sh8[0] = r;
    }
    __syncthreads();
    float res = sh8[0];
    __syncthreads();
    return res;
}
__global__ void ln_kernel(const float* __restrict__ x, const float* __restrict__ gamma,
                          const float* __restrict__ beta) {
    __shared__ float sh[8];
    int t = blockIdx.x, d4 = threadIdx.x;
    float4 v = reinterpret_cast<const float4*>(x + (size_t)t * DMODEL)[d4];
    float mu = blockReduceSum256(v.x + v.y + v.z + v.w, sh) * (1.0f / DMODEL);
    float dx = v.x - mu, dy = v.y - mu, dz = v.z - mu, dw = v.w - mu;
    float var = blockReduceSum256(dx*dx + dy*dy + dz*dz + dw*dw, sh) * (1.0f / DMODEL);
    float inv = rsqrtf(var + 1e-5f);
    float4 gg = reinterpret_cast<const float4*>(gamma)[d4];
    float4 bb = reinterpret_cast<const float4*>(beta)[d4];
    float4 o;
    o.x = dx*inv*gg.x + bb.x; o.y = dy*inv*gg.y + bb.y;
    o.z = dz*inv*gg.z + bb.z; o.w = dw*inv*gg.w + bb.w;
    reinterpret_cast<float4*>(g_h + (size_t)t * DMODEL)[d4] = o;
    float4 r;
    r.x = tf32r(o.x); r.y = tf32r(o.y); r.z = tf32r(o.z); r.w = tf32r(o.w);
    reinterpret_cast<float4*>(g_ht + (size_t)t * DMODEL)[d4] = r;
}

// ---------------- Router (fp64 accum, bit-stable top-2) ----------------
__global__ void router_kernel(const float* __restrict__ Wr) {
    int gw = (blockIdx.x * blockDim.x + threadIdx.x) >> 5;
    int lane = threadIdx.x & 31;
    if (gw >= T_TOK) return;
    const float* hrow = g_h + (size_t)gw * DMODEL;
    double acc[E_ROUTED];
    #pragma unroll
    for (int e = 0; e < E_ROUTED; e++) acc[e] = 0.0;
    for (int d = lane; d < DMODEL; d += 32) {
        float hv = hrow[d];
        const float* wrow = Wr + (size_t)d * E_ROUTED;
        #pragma unroll
        for (int e = 0; e < E_ROUTED; e++) acc[e] += (double)hv * (double)wrow[e];
    }
    #pragma unroll
    for (int e = 0; e < E_ROUTED; e++)
        #pragma unroll
        for (int o = 16; o; o >>= 1) acc[e] += __shfl_down_sync(0xffffffffu, acc[e], o);
    if (lane == 0) {
        float v[E_ROUTED];
        #pragma unroll
        for (int e = 0; e < E_ROUTED; e++) v[e] = (float)acc[e];
        int i1 = 0;
        #pragma unroll
        for (int e = 1; e < E_ROUTED; e++) if (v[e] > v[i1]) i1 = e;
        int i2 = -1;
        #pragma unroll
        for (int e = 0; e < E_ROUTED; e++) {
            if (e == i1) continue;
            if (i2 < 0 || v[e] > v[i2]) i2 = e;
        }
        float m = v[i1], e1 = expf(v[i1]-m), e2 = expf(v[i2]-m), inv = 1.0f/(e1+e2);
        g_topidx[gw*2+0] = i1; g_topidx[gw*2+1] = i2;
        g_gate[gw*2+0] = e1*inv; g_gate[gw*2+1] = e2*inv;
    }
}

// ---------------- Dispatch positions ----------------
__global__ void pos_kernel() {
    int e = blockIdx.x;
    __shared__ int warpTot[8];
    int lane = threadIdx.x & 31, wid = threadIdx.x >> 5;
    int running = 0;
    for (int k = 0; k < TOPK; k++)
        for (int base = 0; base < T_TOK; base += 256) {
            int t = base + threadIdx.x;
            int match = (g_topidx[t*2+k] == e) ? 1 : 0;
            unsigned bal = __ballot_sync(0xffffffffu, match);
            int wpre = __popc(bal & ((1u << lane) - 1u));
            if (lane == 31) warpTot[wid] = wpre + match;
            __syncthreads();
            int wbase = 0;
            #pragma unroll
            for (int w = 0; w < 8; w++) if (w < wid) wbase += warpTot[w];
            if (match) {
                int p = running + wbase + wpre;
                if (p < CAPACITY) { g_pos[k*T_TOK+t] = p; g_slot_token[e*CAPACITY+p] = t; }
                else g_pos[k*T_TOK+t] = -1;
            }
            int tot = 0;
            #pragma unroll
            for (int w = 0; w < 8; w++) tot += warpTot[w];
            running += tot;
            __syncthreads();
        }
    if (threadIdx.x == 0) g_count[e] = (running < CAPACITY) ? running : CAPACITY;
}

// ---------------- Weight transpose to K-major + tf32 round ----------------
__global__ void transpose_kernel(const float* __restrict__ src, int which, int ebase,
                                 int R, int C) {
    __shared__ float t[32][33];
    float* dstb = (which == 0) ? g_W1t : (which == 1) ? g_W3t : g_W2t;
    int b = blockIdx.z;
    const float* s = src + (size_t)b * R * C;
    float* d = dstb + (size_t)(ebase + b) * R * C;
    int tx = threadIdx.x, ty = threadIdx.y;
    #pragma unroll
    for (int i = 0; i < 32; i += 8)
        t[ty+i][tx] = s[(size_t)(blockIdx.y*32 + ty + i) * C + blockIdx.x*32 + tx];
    __syncthreads();
    #pragma unroll
    for (int i = 0; i < 32; i += 8)
        d[(size_t)(blockIdx.x*32 + ty + i) * R + blockIdx.y*32 + tx] = tf32r(t[tx][ty+i]);
}

// ================= Fused W1+W3 tf32 mma.sync GEMM + SwiGLU =================
// BM=128, BN=64 per matrix (W1 and W3 together), BK=32, 256 thr (8 warps 4x2)
#define LDA 36
#define G13_SMEM ((2*128 + 2*64 + 2*64) * LDA * 4)   // 73728 B

__global__ void __launch_bounds__(256, 1) gemm13_mma() {
    extern __shared__ float sm[];
    float* sA  = sm;                       // 2 stages * 128 rows * 36
    float* sB1 = sm + 2*128*LDA;           // 2 * 64 * 36
    float* sB3 = sB1 + 2*64*LDA;
    const int e = blockIdx.z;
    const int n0 = blockIdx.x * 64;
    const int m0 = blockIdx.y * 128;
    const int cnt = (e < E_ROUTED) ? g_count[e] : T_TOK;
    if (m0 >= cnt) return;
    const int tid = threadIdx.x, wid = tid >> 5, lane = tid & 31;
    const int wm = wid >> 1, wn = wid & 1;
    const int gid = lane >> 2, t4 = lane & 3;
    const int seg = tid & 7, lrow = tid >> 3;   // loader mapping

    const float* aptr[4];
    #pragma unroll
    for (int i = 0; i < 4; i++) {
        int mg = m0 + lrow + 32*i;
        int tok = (e < E_ROUTED) ? ((mg < cnt) ? g_slot_token[e*CAPACITY + mg] : 0) : mg;
        aptr[i] = g_ht + (size_t)tok * DMODEL + seg*4;
    }
    const float* b1p[2];
    const float* b3p[2];
    {
        const float* w1 = g_W1t + (size_t)e * DFF * DMODEL + (size_t)n0 * DMODEL + seg*4;
        const float* w3 = g_W3t + (size_t)e * DFF * DMODEL + (size_t)n0 * DMODEL + seg*4;
        #pragma unroll
        for (int i = 0; i < 2; i++) {
            b1p[i] = w1 + (size_t)(lrow + 32*i) * DMODEL;
            b3p[i] = w3 + (size_t)(lrow + 32*i) * DMODEL;
        }
    }
    const uint32_t sAu  = smem_u32(sA)  + (lrow*LDA + seg*4) * 4;
    const uint32_t sB1u = smem_u32(sB1) + (lrow*LDA + seg*4) * 4;
    const uint32_t sB3u = smem_u32(sB3) + (lrow*LDA + seg*4) * 4;

    float c1[2][4][4] = {};
    float c3[2][4][4] = {};

    auto load_stage = [&](int s, int j) {
        uint32_t ao = sAu + s*128*LDA*4;
        #pragma unroll
        for (int i = 0; i < 4; i++) cp16(ao + i*32*LDA*4, aptr[i] + j*32);
        uint32_t b1o = sB1u + s*64*LDA*4, b3o = sB3u + s*64*LDA*4;
        #pragma unroll
        for (int i = 0; i < 2; i++) {
            cp16(b1o + i*32*LDA*4, b1p[i] + j*32);
            cp16(b3o + i*32*LDA*4, b3p[i] + j*32);
        }
        cp_commit();
    };
    auto compute = [&](int s) {
        const uint32_t* A  = (const uint32_t*)(sA  + (s*128 + wm*32) * LDA);
        const uint32_t* B1 = (const uint32_t*)(sB1 + (s*64  + wn*32) * LDA);
        const uint32_t* B3 = (const uint32_t*)(sB3 + (s*64  + wn*32) * LDA);
        #pragma unroll
        for (int ks = 0; ks < 4; ks++) {
            const int kc = ks*8 + t4;
            uint32_t a[2][4];
            #pragma unroll
            for (int t = 0; t < 2; t++) {
                int r = t*16 + gid;
                a[t][0] = A[r*LDA + kc];
                a[t][1] = A[(r+8)*LDA + kc];
                a[t][2] = A[r*LDA + kc + 4];
                a[t][3] = A[(r+8)*LDA + kc + 4];
            }
            #pragma unroll
            for (int u = 0; u < 4; u++) {
                uint32_t p0 = B1[(u*8+gid)*LDA + kc], p1 = B1[(u*8+gid)*LDA + kc + 4];
                uint32_t q0 = B3[(u*8+gid)*LDA + kc], q1 = B3[(u*8+gid)*LDA + kc + 4];
                #pragma unroll
                for (int t = 0; t < 2; t++) {
                    mma_tf32(c1[t][u], a[t][0], a[t][1], a[t][2], a[t][3], p0, p1);
                    mma_tf32(c3[t][u], a[t][0], a[t][1], a[t][2], a[t][3], q0, q1);
                }
            }
        }
    };

    load_stage(0, 0);
    #pragma unroll 1
    for (int j = 0; j < DMODEL/32; ++j) {
        if (j + 1 < DMODEL/32) { load_stage((j+1) & 1, j+1); cp_wait<1>(); }
        else cp_wait<0>();
        __syncthreads();
        compute(j & 1);
        __syncthreads();
    }

    float* dstb = (e < E_ROUTED) ? g_ub + (size_t)e * CAPACITY * DFF : g_ubs;
    #pragma unroll
    for (int t = 0; t < 2; t++)
        #pragma unroll
        for (int half = 0; half < 2; half++) {
            int r = m0 + wm*32 + t*16 + gid + half*8;
            if (r < cnt) {
                float* drow = dstb + (size_t)r * DFF + n0 + wn*32 + t4*2;
                #pragma unroll
                for (int u = 0; u < 4; u++) {
                    int ci = half*2;
                    float2 o;
                    o.x = tf32r(silu_f(c1[t][u][ci])   * c3[t][u][ci]);
                    o.y = tf32r(silu_f(c1[t][u][ci+1]) * c3[t][u][ci+1]);
                    *reinterpret_cast<float2*>(drow + u*8) = o;
                }
            }
        }
}

// ================= W2 tf32 mma.sync GEMM =================
// BM=128, BN=128, BK=32, warp tile 32x64
#define G2_SMEM ((2*128 + 2*128) * LDA * 4)   // 73728 B

__global__ void __launch_bounds__(256, 1) gemm2_mma() {
    extern __shared__ float sm[];
    float* sA = sm;
    float* sB = sm + 2*128*LDA;
    const int e = blockIdx.z;
    const int n0 = blockIdx.x * 128;
    const int m0 = blockIdx.y * 128;
    const int cnt = (e < E_ROUTED) ? g_count[e] : T_TOK;
    if (m0 >= cnt) return;
    const int tid = threadIdx.x, wid = tid >> 5, lane = tid & 31;
    const int wm = wid >> 1, wn = wid & 1;
    const int gid = lane >> 2, t4 = lane & 3;
    const int seg = tid & 7, lrow = tid >> 3;

    const float* Abase = (e < E_ROUTED) ? g_ub + (size_t)e * CAPACITY * DFF : g_ubs;
    const float* aptr[4];
    #pragma unroll
    for (int i = 0; i < 4; i++) {
        int mg = m0 + lrow + 32*i;
        aptr[i] = Abase + (size_t)((mg < cnt) ? mg : 0) * DFF + seg*4;
    }
    const float* bptr[4];
    {
        const float* w2 = g_W2t + (size_t)e * DMODEL * DFF + (size_t)n0 * DFF + seg*4;
        #pragma unroll
        for (int i = 0; i < 4; i++) bptr[i] = w2 + (size_t)(lrow + 32*i) * DFF;
    }
    const uint32_t sAu = smem_u32(sA) + (lrow*LDA + seg*4) * 4;
    const uint32_t sBu = smem_u32(sB) + (lrow*LDA + seg*4) * 4;

    float c[2][8][4] = {};

    auto load_stage = [&](int s, int j) {
        uint32_t ao = sAu + s*128*LDA*4, bo = sBu + s*128*LDA*4;
        #pragma unroll
        for (int i = 0; i < 4; i++) {
            cp16(ao + i*32*LDA*4, aptr[i] + j*32);
            cp16(bo + i*32*LDA*4, bptr[i] + j*32);
        }
        cp_commit();
    };
    auto compute = [&](int s) {
        const uint32_t* A = (const uint32_t*)(sA + (s*128 + wm*32) * LDA);
        const uint32_t* B = (const uint32_t*)(sB + (s*128 + wn*64) * LDA);
        #pragma unroll
        for (int ks = 0; ks < 4; ks++) {
            const int kc = ks*8 + t4;
            uint32_t a[2][4];
            #pragma unroll
            for (int t = 0; t < 2; t++) {
                int r = t*16 + gid;
                a[t][0] = A[r*LDA + kc];
                a[t][1] = A[(r+8)*LDA + kc];
                a[t][2] = A[r*LDA + kc + 4];
                a[t][3] = A[(r+8)*LDA + kc + 4];
            }
            #pragma unroll
            for (int u = 0; u < 8; u++) {
                uint32_t b0 = B[(u*8+gid)*LDA + kc], b1 = B[(u*8+gid)*LDA + kc + 4];
                #pragma unroll
                for (int t = 0; t < 2; t++)
                    mma_tf32(c[t][u], a[t][0], a[t][1], a[t][2], a[t][3], b0, b1);
            }
        }
    };

    load_stage(0, 0);
    #pragma unroll 1
    for (int j = 0; j < DFF/32; ++j) {
        if (j + 1 < DFF/32) { load_stage((j+1) & 1, j+1); cp_wait<1>(); }
        else cp_wait<0>();
        __syncthreads();
        compute(j & 1);
        __syncthreads();
    }

    float* dstb = (e < E_ROUTED) ? g_ye + (size_t)e * CAPACITY * DMODEL : g_ys;
    #pragma unroll
    for (int t = 0; t < 2; t++)
        #pragma unroll
        for (int half = 0; half < 2; half++) {
            int r = m0 + wm*32 + t*16 + gid + half*8;
            if (r < cnt) {
                float* drow = dstb + (size_t)r * DMODEL + n0 + wn*64 + t4*2;
                #pragma unroll
                for (int u = 0; u < 8; u++) {
                    int ci = half*2;
                    float2 o; o.x = c[t][u][ci]; o.y = c[t][u][ci+1];
                    *reinterpret_cast<float2*>(drow + u*8) = o;
                }
            }
        }
}

// ---------------- Combine ----------------
__global__ void combine_kernel(float* __restrict__ out) {
    int t = blockIdx.x, d4 = threadIdx.x;
    float4 o = reinterpret_cast<const float4*>(g_ys + (size_t)t * DMODEL)[d4];
    #pragma unroll
    for (int k = 0; k < TOPK; k++) {
        int p = g_pos[k * T_TOK + t];
        if (p >= 0) {
            int e = g_topidx[t*2+k];
            float gv = g_gate[t*2+k];
            float4 y = reinterpret_cast<const float4*>(g_ye + ((size_t)e*CAPACITY + p) * DMODEL)[d4];
            o.x += gv*y.x; o.y += gv*y.y; o.z += gv*y.z; o.w += gv*y.w;
        }
    }
    reinterpret_cast<float4*>(out + (size_t)t * DMODEL)[d4] = o;
}

// ---------------- launch ----------------
extern "C" void kernel_launch(void* const* d_in, const int* in_sizes, int n_in,
                              void* d_out, int out_size) {
    (void)in_sizes; (void)n_in; (void)out_size;
    const float* x    = (const float*)d_in[0];
    const float* ln_g = (const float*)d_in[1];
    const float* ln_b = (const float*)d_in[2];
    const float* Wr   = (const float*)d_in[3];
    const float* W1   = (const float*)d_in[4];
    const float* W3   = (const float*)d_in[5];
    const float* W2   = (const float*)d_in[6];
    const float* W1s  = (const float*)d_in[7];
    const float* W3s  = (const float*)d_in[8];
    const float* W2s  = (const float*)d_in[9];
    float* out = (float*)d_out;

    cudaFuncSetAttribute(gemm13_mma, cudaFuncAttributeMaxDynamicSharedMemorySize, G13_SMEM);
    cudaFuncSetAttribute(gemm2_mma,  cudaFuncAttributeMaxDynamicSharedMemorySize, G2_SMEM);

    ln_kernel<<<T_TOK, 256>>>(x, ln_g, ln_b);
    router_kernel<<<T_TOK / 8, 256>>>(Wr);
    pos_kernel<<<E_ROUTED, 256>>>();

    dim3 tb(32, 8);
    transpose_kernel<<<dim3(DFF/32, DMODEL/32, E_ROUTED), tb>>>(W1, 0, 0, DMODEL, DFF);
    transpose_kernel<<<dim3(DFF/32, DMODEL/32, 1), tb>>>(W1s, 0, E_ROUTED, DMODEL, DFF);
    transpose_kernel<<<dim3(DFF/32, DMODEL/32, E_ROUTED), tb>>>(W3, 1, 0, DMODEL, DFF);
    transpose_kernel<<<dim3(DFF/32, DMODEL/32, 1), tb>>>(W3s, 1, E_ROUTED, DMODEL, DFF);
    transpose_kernel<<<dim3(DMODEL/32, DFF/32, E_ROUTED), tb>>>(W2, 2, 0, DFF, DMODEL);
    transpose_kernel<<<dim3(DMODEL/32, DFF/32, 1), tb>>>(W2s, 2, E_ROUTED, DFF, DMODEL);

    gemm13_mma<<<dim3(DFF/64, T_TOK/128, E_ROUTED + 1), 256, G13_SMEM>>>();
    gemm2_mma <<<dim3(DMODEL/128, T_TOK/128, E_ROUTED + 1), 256, G2_SMEM>>>();

    combine_kernel<<<T_TOK, 256>>>(out);
}

// round 5
// speedup vs baseline: 3.2815x; 1.1669x over previous
#include <cuda_runtime.h>
#include <math.h>
#include <stdint.h>

#define T_TOK     8192
#define DMODEL    1024
#define DFF       4096
#define E_ROUTED  7
#define TOPK      2
#define CAPACITY  2926

// ---------------- scratch ----------------
__device__ float g_h [(size_t)T_TOK * DMODEL];   // exact LN output (router)
__device__ float g_ht[(size_t)T_TOK * DMODEL];   // tf32-rounded LN output (GEMM A)
__device__ int   g_topidx[T_TOK * TOPK];
__device__ float g_gate[T_TOK * TOPK];
__device__ int   g_pos[TOPK * T_TOK];
__device__ int   g_slot_token[E_ROUTED * CAPACITY];
__device__ int   g_count[E_ROUTED];
__device__ float g_ub [(size_t)E_ROUTED * CAPACITY * DFF];  // u = silu(a)*b, tf32-rounded
__device__ float g_ubs[(size_t)T_TOK * DFF];
__device__ float g_ye [(size_t)E_ROUTED * CAPACITY * DMODEL];
__device__ float g_ys [(size_t)T_TOK * DMODEL];

// ---------------- helpers ----------------
__device__ __forceinline__ uint32_t smem_u32(const void* p) {
    return (uint32_t)__cvta_generic_to_shared(p);
}
__device__ __forceinline__ float tf32r(float x) {
    uint32_t u;
    asm("cvt.rna.tf32.f32 %0, %1;" : "=r"(u) : "f"(x));
    return __uint_as_float(u);
}
__device__ __forceinline__ uint32_t tf32u(float x) {
    uint32_t u;
    asm("cvt.rna.tf32.f32 %0, %1;" : "=r"(u) : "f"(x));
    return u;
}
__device__ __forceinline__ void cp16(uint32_t d, const float* s) {
    asm volatile("cp.async.cg.shared.global [%0], [%1], 16;" :: "r"(d), "l"(s) : "memory");
}
__device__ __forceinline__ void cp_commit() {
    asm volatile("cp.async.commit_group;" ::: "memory");
}
template <int N>
__device__ __forceinline__ void cp_wait() {
    asm volatile("cp.async.wait_group %0;" :: "n"(N) : "memory");
}
__device__ __forceinline__ void mma_tf32(float c[4], uint32_t a0, uint32_t a1,
                                         uint32_t a2, uint32_t a3,
                                         uint32_t b0, uint32_t b1) {
    asm volatile(
        "mma.sync.aligned.m16n8k8.row.col.f32.tf32.tf32.f32 "
        "{%0,%1,%2,%3},{%4,%5,%6,%7},{%8,%9},{%0,%1,%2,%3};"
        : "+f"(c[0]), "+f"(c[1]), "+f"(c[2]), "+f"(c[3])
        : "r"(a0), "r"(a1), "r"(a2), "r"(a3), "r"(b0), "r"(b1));
}
__device__ __forceinline__ float silu_f(float v) { return v / (1.0f + __expf(-v)); }

// ---------------- LayerNorm ----------------
__device__ __forceinline__ float blockReduceSum256(float v, float* sh8) {
    int lane = threadIdx.x & 31, wid = threadIdx.x >> 5;
    #pragma unroll
    for (int o = 16; o; o >>= 1) v += __shfl_down_sync(0xffffffffu, v, o);
    if (lane == 0) sh8[wid] = v;
    __syncthreads();
    float r = (threadIdx.x < 8) ? sh8[threadIdx.x] : 0.0f;
    if (wid == 0) {
        #pragma unroll
        for (int o = 4; o; o >>= 1) r += __shfl_down_sync(0xffffffffu, r, o);
        if (lane == 0) sh8[0] = r;
    }
    __syncthreads();
    float res = sh8[0];
    __syncthreads();
    return res;
}
__global__ void ln_kernel(const float* __restrict__ x, const float* __restrict__ gamma,
                          const float* __restrict__ beta) {
    __shared__ float sh[8];
    int t = blockIdx.x, d4 = threadIdx.x;
    float4 v = reinterpret_cast<const float4*>(x + (size_t)t * DMODEL)[d4];
    float mu = blockReduceSum256(v.x + v.y + v.z + v.w, sh) * (1.0f / DMODEL);
    float dx = v.x - mu, dy = v.y - mu, dz = v.z - mu, dw = v.w - mu;
    float var = blockReduceSum256(dx*dx + dy*dy + dz*dz + dw*dw, sh) * (1.0f / DMODEL);
    float inv = rsqrtf(var + 1e-5f);
    float4 gg = reinterpret_cast<const float4*>(gamma)[d4];
    float4 bb = reinterpret_cast<const float4*>(beta)[d4];
    float4 o;
    o.x = dx*inv*gg.x + bb.x; o.y = dy*inv*gg.y + bb.y;
    o.z = dz*inv*gg.z + bb.z; o.w = dw*inv*gg.w + bb.w;
    reinterpret_cast<float4*>(g_h + (size_t)t * DMODEL)[d4] = o;
    float4 r;
    r.x = tf32r(o.x); r.y = tf32r(o.y); r.z = tf32r(o.z); r.w = tf32r(o.w);
    reinterpret_cast<float4*>(g_ht + (size_t)t * DMODEL)[d4] = r;
}

// ---------------- Router (fp64 accum, bit-stable top-2) ----------------
__global__ void router_kernel(const float* __restrict__ Wr, int tok0) {
    int gw = tok0 + ((blockIdx.x * blockDim.x + threadIdx.x) >> 5);
    int lane = threadIdx.x & 31;
    if (gw >= T_TOK) return;
    const float* hrow = g_h + (size_t)gw * DMODEL;
    double acc[E_ROUTED];
    #pragma unroll
    for (int e = 0; e < E_ROUTED; e++) acc[e] = 0.0;
    for (int d = lane; d < DMODEL; d += 32) {
        float hv = hrow[d];
        const float* wrow = Wr + (size_t)d * E_ROUTED;
        #pragma unroll
        for (int e = 0; e < E_ROUTED; e++) acc[e] += (double)hv * (double)wrow[e];
    }
    #pragma unroll
    for (int e = 0; e < E_ROUTED; e++)
        #pragma unroll
        for (int o = 16; o; o >>= 1) acc[e] += __shfl_down_sync(0xffffffffu, acc[e], o);
    if (lane == 0) {
        float v[E_ROUTED];
        #pragma unroll
        for (int e = 0; e < E_ROUTED; e++) v[e] = (float)acc[e];
        int i1 = 0;
        #pragma unroll
        for (int e = 1; e < E_ROUTED; e++) if (v[e] > v[i1]) i1 = e;
        int i2 = -1;
        #pragma unroll
        for (int e = 0; e < E_ROUTED; e++) {
            if (e == i1) continue;
            if (i2 < 0 || v[e] > v[i2]) i2 = e;
        }
        float m = v[i1], e1 = expf(v[i1]-m), e2 = expf(v[i2]-m), inv = 1.0f/(e1+e2);
        g_topidx[gw*2+0] = i1; g_topidx[gw*2+1] = i2;
        g_gate[gw*2+0] = e1*inv; g_gate[gw*2+1] = e2*inv;
    }
}

// ---------------- Dispatch positions ----------------
__global__ void pos_kernel(int ebase) {
    int e = ebase + blockIdx.x;
    __shared__ int warpTot[8];
    int lane = threadIdx.x & 31, wid = threadIdx.x >> 5;
    int running = 0;
    for (int k = 0; k < TOPK; k++)
        for (int base = 0; base < T_TOK; base += 256) {
            int t = base + threadIdx.x;
            int match = (g_topidx[t*2+k] == e) ? 1 : 0;
            unsigned bal = __ballot_sync(0xffffffffu, match);
            int wpre = __popc(bal & ((1u << lane) - 1u));
            if (lane == 31) warpTot[wid] = wpre + match;
            __syncthreads();
            int wbase = 0;
            #pragma unroll
            for (int w = 0; w < 8; w++) if (w < wid) wbase += warpTot[w];
            if (match) {
                int p = running + wbase + wpre;
                if (p < CAPACITY) { g_pos[k*T_TOK+t] = p; g_slot_token[e*CAPACITY+p] = t; }
                else g_pos[k*T_TOK+t] = -1;
            }
            int tot = 0;
            #pragma unroll
            for (int w = 0; w < 8; w++) tot += warpTot[w];
            running += tot;
            __syncthreads();
        }
    if (threadIdx.x == 0) g_count[e] = (running < CAPACITY) ? running : CAPACITY;
}

// ================= Fused W1+W3 tf32 mma.sync GEMM + SwiGLU =================
// BM=128, BN=64 (each of W1/W3), BK=32. B tiles loaded DIRECTLY from row-major
// [K][N] weights (no pre-transpose); fragments read as Bs[kc][n], tf32-rounded
// in-register.
#define LDA   36
#define LDB13 72
#define G13_SMEM ((2*128*LDA + 4*32*LDB13) * 4)   // 73728 B

__global__ void __launch_bounds__(256, 2) gemm13_mma(
    const float* __restrict__ W1, const float* __restrict__ W3,
    const float* __restrict__ W1s, const float* __restrict__ W3s)
{
    extern __shared__ float sm[];
    float* sA  = sm;                      // 2 stages * 128 * LDA
    float* sB1 = sm + 2*128*LDA;          // 2 * 32 * LDB13
    float* sB3 = sB1 + 2*32*LDB13;
    const int e = blockIdx.z;
    const int n0 = blockIdx.x * 64;
    const int m0 = blockIdx.y * 128;
    const int cnt = (e < E_ROUTED) ? g_count[e] : T_TOK;
    if (m0 >= cnt) return;
    const int tid = threadIdx.x, wid = tid >> 5, lane = tid & 31;
    const int wm = wid >> 1, wn = wid & 1;
    const int gid = lane >> 2, t4 = lane & 3;

    const float* w1e = (e < E_ROUTED) ? W1 + (size_t)e * DMODEL * DFF : W1s;
    const float* w3e = (e < E_ROUTED) ? W3 + (size_t)e * DMODEL * DFF : W3s;

    // loader mappings
    const float* ag[4]; uint32_t aoff[4];
    #pragma unroll
    for (int i = 0; i < 4; i++) {
        int idx = tid + i*256;
        int r = idx >> 3, s = idx & 7;
        int mg = m0 + r;
        int tok = (e < E_ROUTED) ? ((mg < cnt) ? g_slot_token[e*CAPACITY + mg] : 0) : mg;
        ag[i] = g_ht + (size_t)tok * DMODEL + s*4;
        aoff[i] = (uint32_t)(r*LDA + s*4) * 4;
    }
    const float* b1g[2]; const float* b3g[2]; uint32_t boff[2];
    #pragma unroll
    for (int i = 0; i < 2; i++) {
        int idx = tid + i*256;
        int kr = idx >> 4, s = idx & 15;
        b1g[i] = w1e + (size_t)kr * DFF + n0 + s*4;
        b3g[i] = w3e + (size_t)kr * DFF + n0 + s*4;
        boff[i] = (uint32_t)(kr*LDB13 + s*4) * 4;
    }
    const uint32_t sAu  = smem_u32(sA);
    const uint32_t sB1u = smem_u32(sB1);
    const uint32_t sB3u = smem_u32(sB3);

    float c1[2][4][4] = {};
    float c3[2][4][4] = {};

    auto load_stage = [&](int s, int j) {
        uint32_t ao = sAu + (uint32_t)s*128*LDA*4;
        #pragma unroll
        for (int i = 0; i < 4; i++) cp16(ao + aoff[i], ag[i] + j*32);
        uint32_t b1o = sB1u + (uint32_t)s*32*LDB13*4;
        uint32_t b3o = sB3u + (uint32_t)s*32*LDB13*4;
        size_t roff = (size_t)j * 32 * DFF;
        #pragma unroll
        for (int i = 0; i < 2; i++) {
            cp16(b1o + boff[i], b1g[i] + roff);
            cp16(b3o + boff[i], b3g[i] + roff);
        }
        cp_commit();
    };
    auto compute = [&](int s) {
        const uint32_t* A  = (const uint32_t*)(sA + (s*128 + wm*32) * LDA);
        const float*    B1 = sB1 + s*32*LDB13 + wn*32;
        const float*    B3 = sB3 + s*32*LDB13 + wn*32;
        #pragma unroll
        for (int ks = 0; ks < 4; ks++) {
            const int kc = ks*8 + t4;
            uint32_t a[2][4];
            #pragma unroll
            for (int t = 0; t < 2; t++) {
                int r = t*16 + gid;
                a[t][0] = A[r*LDA + kc];
                a[t][1] = A[(r+8)*LDA + kc];
                a[t][2] = A[r*LDA + kc + 4];
                a[t][3] = A[(r+8)*LDA + kc + 4];
            }
            #pragma unroll
            for (int u = 0; u < 4; u++) {
                const int n = u*8 + gid;
                uint32_t p0 = tf32u(B1[kc*LDB13 + n]);
                uint32_t p1 = tf32u(B1[(kc+4)*LDB13 + n]);
                uint32_t q0 = tf32u(B3[kc*LDB13 + n]);
                uint32_t q1 = tf32u(B3[(kc+4)*LDB13 + n]);
                #pragma unroll
                for (int t = 0; t < 2; t++) {
                    mma_tf32(c1[t][u], a[t][0], a[t][1], a[t][2], a[t][3], p0, p1);
                    mma_tf32(c3[t][u], a[t][0], a[t][1], a[t][2], a[t][3], q0, q1);
                }
            }
        }
    };

    load_stage(0, 0);
    #pragma unroll 1
    for (int j = 0; j < DMODEL/32; ++j) {
        if (j + 1 < DMODEL/32) { load_stage((j+1) & 1, j+1); cp_wait<1>(); }
        else cp_wait<0>();
        __syncthreads();
        compute(j & 1);
        __syncthreads();
    }

    float* dstb = (e < E_ROUTED) ? g_ub + (size_t)e * CAPACITY * DFF : g_ubs;
    #pragma unroll
    for (int t = 0; t < 2; t++)
        #pragma unroll
        for (int half = 0; half < 2; half++) {
            int r = m0 + wm*32 + t*16 + gid + half*8;
            if (r < cnt) {
                float* drow = dstb + (size_t)r * DFF + n0 + wn*32 + t4*2;
                #pragma unroll
                for (int u = 0; u < 4; u++) {
                    int ci = half*2;
                    float2 o;
                    o.x = tf32r(silu_f(c1[t][u][ci])   * c3[t][u][ci]);
                    o.y = tf32r(silu_f(c1[t][u][ci+1]) * c3[t][u][ci+1]);
                    *reinterpret_cast<float2*>(drow + u*8) = o;
                }
            }
        }
}

// ================= W2 tf32 mma.sync GEMM =================
// BM=128, BN=128, BK=32; B direct from row-major [F][D]
#define LDB2 136
#define G2_SMEM ((2*128*LDA + 2*32*LDB2) * 4)   // 71680 B

__global__ void __launch_bounds__(256, 2) gemm2_mma(
    const float* __restrict__ W2, const float* __restrict__ W2s)
{
    extern __shared__ float sm[];
    float* sA = sm;                    // 2 * 128 * LDA
    float* sB = sm + 2*128*LDA;        // 2 * 32 * LDB2
    const int e = blockIdx.z;
    const int n0 = blockIdx.x * 128;
    const int m0 = blockIdx.y * 128;
    const int cnt = (e < E_ROUTED) ? g_count[e] : T_TOK;
    if (m0 >= cnt) return;
    const int tid = threadIdx.x, wid = tid >> 5, lane = tid & 31;
    const int wm = wid >> 1, wn = wid & 1;
    const int gid = lane >> 2, t4 = lane & 3;

    const float* Abase = (e < E_ROUTED) ? g_ub + (size_t)e * CAPACITY * DFF : g_ubs;
    const float* w2e = (e < E_ROUTED) ? W2 + (size_t)e * DFF * DMODEL : W2s;

    const float* ag[4]; uint32_t aoff[4];
    #pragma unroll
    for (int i = 0; i < 4; i++) {
        int idx = tid + i*256;
        int r = idx >> 3, s = idx & 7;
        int mg = m0 + r;
        ag[i] = Abase + (size_t)((mg < cnt) ? mg : 0) * DFF + s*4;
        aoff[i] = (uint32_t)(r*LDA + s*4) * 4;
    }
    const float* bg[4]; uint32_t boff[4];
    #pragma unroll
    for (int i = 0; i < 4; i++) {
        int idx = tid + i*256;
        int kr = idx >> 5, s = idx & 31;
        bg[i] = w2e + (size_t)kr * DMODEL + n0 + s*4;
        boff[i] = (uint32_t)(kr*LDB2 + s*4) * 4;
    }
    const uint32_t sAu = smem_u32(sA);
    const uint32_t sBu = smem_u32(sB);

    float c[2][8][4] = {};

    auto load_stage = [&](int s, int j) {
        uint32_t ao = sAu + (uint32_t)s*128*LDA*4;
        uint32_t bo = sBu + (uint32_t)s*32*LDB2*4;
        size_t roff = (size_t)j * 32 * DMODEL;
        #pragma unroll
        for (int i = 0; i < 4; i++) {
            cp16(ao + aoff[i], ag[i] + j*32);
            cp16(bo + boff[i], bg[i] + roff);
        }
        cp_commit();
    };
    auto compute = [&](int s) {
        const uint32_t* A = (const uint32_t*)(sA + (s*128 + wm*32) * LDA);
        const float*    B = sB + s*32*LDB2 + wn*64;
        #pragma unroll
        for (int ks = 0; ks < 4; ks++) {
            const int kc = ks*8 + t4;
            uint32_t a[2][4];
            #pragma unroll
            for (int t = 0; t < 2; t++) {
                int r = t*16 + gid;
                a[t][0] = A[r*LDA + kc];
                a[t][1] = A[(r+8)*LDA + kc];
                a[t][2] = A[r*LDA + kc + 4];
                a[t][3] = A[(r+8)*LDA + kc + 4];
            }
            #pragma unroll
            for (int u = 0; u < 8; u++) {
                const int n = u*8 + gid;
                uint32_t b0 = tf32u(B[kc*LDB2 + n]);
                uint32_t b1 = tf32u(B[(kc+4)*LDB2 + n]);
                #pragma unroll
                for (int t = 0; t < 2; t++)
                    mma_tf32(c[t][u], a[t][0], a[t][1], a[t][2], a[t][3], b0, b1);
            }
        }
    };

    load_stage(0, 0);
    #pragma unroll 1
    for (int j = 0; j < DFF/32; ++j) {
        if (j + 1 < DFF/32) { load_stage((j+1) & 1, j+1); cp_wait<1>(); }
        else cp_wait<0>();
        __syncthreads();
        compute(j & 1);
        __syncthreads();
    }

    float* dstb = (e < E_ROUTED) ? g_ye + (size_t)e * CAPACITY * DMODEL : g_ys;
    #pragma unroll
    for (int t = 0; t < 2; t++)
        #pragma unroll
        for (int half = 0; half < 2; half++) {
            int r = m0 + wm*32 + t*16 + gid + half*8;
            if (r < cnt) {
                float* drow = dstb + (size_t)r * DMODEL + n0 + wn*64 + t4*2;
                #pragma unroll
                for (int u = 0; u < 8; u++) {
                    int ci = half*2;
                    float2 o; o.x = c[t][u][ci]; o.y = c[t][u][ci+1];
                    *reinterpret_cast<float2*>(drow + u*8) = o;
                }
            }
        }
}

// ---------------- Combine ----------------
__global__ void combine_kernel(float* __restrict__ out) {
    int t = blockIdx.x, d4 = threadIdx.x;
    float4 o = reinterpret_cast<const float4*>(g_ys + (size_t)t * DMODEL)[d4];
    #pragma unroll
    for (int k = 0; k < TOPK; k++) {
        int p = g_pos[k * T_TOK + t];
        if (p >= 0) {
            int e = g_topidx[t*2+k];
            float gv = g_gate[t*2+k];
            float4 y = reinterpret_cast<const float4*>(g_ye + ((size_t)e*CAPACITY + p) * DMODEL)[d4];
            o.x += gv*y.x; o.y += gv*y.y; o.z += gv*y.z; o.w += gv*y.w;
        }
    }
    reinterpret_cast<float4*>(out + (size_t)t * DMODEL)[d4] = o;
}

// ---------------- launch ----------------
extern "C" void kernel_launch(void* const* d_in, const int* in_sizes, int n_in,
                              void* d_out, int out_size) {
    (void)in_sizes; (void)n_in; (void)out_size;
    const float* x    = (const float*)d_in[0];
    const float* ln_g = (const float*)d_in[1];
    const float* ln_b = (const float*)d_in[2];
    const float* Wr   = (const float*)d_in[3];
    const float* W1   = (const float*)d_in[4];
    const float* W3   = (const float*)d_in[5];
    const float* W2   = (const float*)d_in[6];
    const float* W1s  = (const float*)d_in[7];
    const float* W3s  = (const float*)d_in[8];
    const float* W2s  = (const float*)d_in[9];
    float* out = (float*)d_out;

    cudaFuncSetAttribute(gemm13_mma, cudaFuncAttributeMaxDynamicSharedMemorySize, G13_SMEM);
    cudaFuncSetAttribute(gemm2_mma,  cudaFuncAttributeMaxDynamicSharedMemorySize, G2_SMEM);

    // launch order arranged so ncu (-s 5 -c 1) profiles gemm13_mma
    ln_kernel<<<T_TOK, 256>>>(x, ln_g, ln_b);                  // 0
    router_kernel<<<T_TOK/16, 256>>>(Wr, 0);                   // 1
    router_kernel<<<T_TOK/16, 256>>>(Wr, T_TOK/2);             // 2
    pos_kernel<<<4, 256>>>(0);                                 // 3
    pos_kernel<<<3, 256>>>(4);                                 // 4

    gemm13_mma<<<dim3(DFF/64, T_TOK/128, E_ROUTED + 1), 256, G13_SMEM>>>(W1, W3, W1s, W3s); // 5
    gemm2_mma <<<dim3(DMODEL/128, T_TOK/128, E_ROUTED + 1), 256, G2_SMEM>>>(W2, W2s);      // 6

    combine_kernel<<<T_TOK, 256>>>(out);                       // 7
}